// round 7
// baseline (speedup 1.0000x reference)
#include <cuda_runtime.h>
#include <string.h>

// HyperConv2dDepthWise: per-batch-weight 5x5 depthwise conv + bias + SiLU
// input:  (16, 128, 128, 128) f32   -> 2048 planes of 128x128
// weights:(16, 3328) f32            -> per (b,c): 25 taps at b*3328+c*25, bias at b*3328+3200+c
// output: (16, 128, 128, 128) f32
//
// Round-6: persistent-plane CTA (grid 2048) + 2-stage cp.async pipeline over
// 4 bands of 32 rows. Staging of band k+1 (LDGSTS, zero-fill OOB) overlaps
// compute of band k. Compute: horizontal f32x2 packing, 5-row packed sliding
// register window, tanh-based packed SiLU epilogue.

#define HW      128
#define BAND    32
#define SROWS   (BAND + 4)     // 36
#define SPITCH  136            // floats; logical col L lives at smem col L+4
#define WSTRIDE 3328           // 25*128 + 128
#define BOFF    3200           // 25*128

typedef unsigned long long ull;

__device__ __forceinline__ ull pair_of(float lo, float hi) {
    float2 t = make_float2(lo, hi);
    ull r;
    memcpy(&r, &t, 8);
    return r;
}
__device__ __forceinline__ void fma2(ull& d, ull a, ull b) {
    asm("fma.rn.f32x2 %0, %1, %2, %0;" : "+l"(d) : "l"(a), "l"(b));
}
__device__ __forceinline__ float2 unpk(ull v) {
    float2 f;
    memcpy(&f, &v, 8);
    return f;
}

// packed SiLU: silu(x) = h + h*tanh(h), h = 0.5*x   (tanh.approx HW op)
__device__ __forceinline__ ull silu2(ull acc, ull half2c) {
    ull h2;
    asm("mul.rn.f32x2 %0, %1, %2;" : "=l"(h2) : "l"(acc), "l"(half2c));
    float2 h = unpk(h2);
    float t0, t1;
    asm("tanh.approx.f32 %0, %1;" : "=f"(t0) : "f"(h.x));
    asm("tanh.approx.f32 %0, %1;" : "=f"(t1) : "f"(h.y));
    ull t2 = pair_of(t0, t1);
    ull r;
    asm("fma.rn.f32x2 %0, %1, %2, %1;" : "=l"(r) : "l"(h2), "l"(t2));
    return r;
}

// One packed window row: covers logical cols x0-2 .. x0+5.
struct WRow {
    ull E0, E1, E2, E3, O0, O1, O2;
};

__device__ __forceinline__ WRow load_row(const float* __restrict__ p) {
    float4 A = *(const float4*)(p);      // logical x0-4 .. x0-1
    float4 B = *(const float4*)(p + 4);  // logical x0   .. x0+3
    float4 C = *(const float4*)(p + 8);  // logical x0+4 .. x0+7
    WRow r;
    memcpy(&r.E0, &A.z, 8);
    memcpy(&r.E1, &B.x, 8);
    memcpy(&r.E2, &B.z, 8);
    memcpy(&r.E3, &C.x, 8);
    r.O0 = pair_of(A.w, B.x);
    r.O1 = pair_of(B.y, B.z);
    r.O2 = pair_of(B.w, C.x);
    return r;
}

// stage one 36-row band (+2-row halo, zero-filled OOB rows) into a smem buffer
__device__ __forceinline__ void stage_band(const float* __restrict__ ip,
                                           float* __restrict__ sbuf,
                                           int r0, int tid)
{
    const int lq = tid & 31;            // interior quad: logical col lq*4
    const int lr = tid >> 5;            // 0..3
#pragma unroll
    for (int k = 0; k < 9; k++) {
        const int y = lr + k * 4;       // 0..35
        const int g = r0 + y - 2;
        const bool ok = (g >= 0 && g < HW);
        const float* src = ip + (ok ? g : 0) * HW + lq * 4;
        const unsigned dst =
            (unsigned)__cvta_generic_to_shared(sbuf + y * SPITCH + 4 + lq * 4);
        const int sz = ok ? 16 : 0;     // src-size 0 -> 16B of zeros
        asm volatile("cp.async.cg.shared.global [%0], [%1], 16, %2;\n"
                     :: "r"(dst), "l"(src), "r"(sz));
    }
    asm volatile("cp.async.commit_group;\n" ::: "memory");
}

__global__ __launch_bounds__(128, 3)
void hconv_dw_kernel(const float* __restrict__ input,
                     const float* __restrict__ wts,
                     float* __restrict__ out)
{
    __shared__ float smem[2][SROWS * SPITCH];

    const int plane = blockIdx.x;       // b*128 + c
    const int b     = plane >> 7;
    const int c     = plane & 127;

    const float* __restrict__ ip = input + (size_t)plane * (HW * HW);
    float* __restrict__ op       = out   + (size_t)plane * (HW * HW);

    const int tid = threadIdx.x;

    // zero halo columns (quads 0 and 33) of BOTH buffers once; staging never
    // writes them, so they remain zero for all bands.
    {
        const float4 z4 = make_float4(0.f, 0.f, 0.f, 0.f);
        if (tid < 2 * SROWS) {                       // buffer 0
            const int y = tid >> 1;
            const int q = (tid & 1) ? 33 : 0;
            *(float4*)(smem[0] + y * SPITCH + q * 4) = z4;
            *(float4*)(smem[1] + y * SPITCH + q * 4) = z4;
        }
    }

    // kick off band 0 load
    stage_band(ip, smem[0], 0, tid);

    // ---- per-plane weights: 25 taps packed (w,w) + bias ----
    const float* wp = wts + b * WSTRIDE + c * 25;
    ull w2[25];
#pragma unroll
    for (int t = 0; t < 25; t++) {
        const float w = __ldg(wp + t);
        w2[t] = pair_of(w, w);
    }
    const float bias = __ldg(wts + b * WSTRIDE + BOFF + c);
    const ull bias2  = pair_of(bias, bias);
    const ull half2c = pair_of(0.5f, 0.5f);

    const int warp = tid >> 5;          // 0..3
    const int lane = tid & 31;
    const int x0   = lane * 4;          // logical output col base
    const int br0  = warp * 8;          // band-local first output row

#pragma unroll
    for (int kb = 0; kb < 4; kb++) {
        const int r0 = kb * BAND;
        float* sbuf = smem[kb & 1];

        if (kb > 0)
            __syncthreads();            // WAR: everyone done reading buf[(kb+1)&1]
        if (kb < 3)
            stage_band(ip, smem[(kb + 1) & 1], r0 + BAND, tid);

        if (kb < 3)
            asm volatile("cp.async.wait_group 1;\n" ::: "memory");
        else
            asm volatile("cp.async.wait_group 0;\n" ::: "memory");
        __syncthreads();                // band kb data visible to all warps

        // ---- compute band kb: warp = full row width, 8 rows per warp ----
        WRow win[5];
#pragma unroll
        for (int y = 0; y < 4; y++)
            win[y] = load_row(sbuf + (br0 + y) * SPITCH + x0);

        float* outp = op + (r0 + br0) * HW + x0;

#pragma unroll
        for (int i = 0; i < 8; i++) {
            // new bottom row -> ring slot (i+4)%5; consumed by last weight row
            win[(i + 4) % 5] = load_row(sbuf + (br0 + i + 4) * SPITCH + x0);

            ull acc0 = bias2, acc1 = bias2;
#pragma unroll
            for (int d = 0; d < 5; d++) {
                const WRow& r = win[(i + d) % 5];
                fma2(acc0, w2[d * 5 + 0], r.E0);  fma2(acc1, w2[d * 5 + 0], r.E1);
                fma2(acc0, w2[d * 5 + 1], r.O0);  fma2(acc1, w2[d * 5 + 1], r.O1);
                fma2(acc0, w2[d * 5 + 2], r.E1);  fma2(acc1, w2[d * 5 + 2], r.E2);
                fma2(acc0, w2[d * 5 + 3], r.O1);  fma2(acc1, w2[d * 5 + 3], r.O2);
                fma2(acc0, w2[d * 5 + 4], r.E2);  fma2(acc1, w2[d * 5 + 4], r.E3);
            }

            const ull s0 = silu2(acc0, half2c);
            const ull s1 = silu2(acc1, half2c);
            float4 o;
            memcpy(&o.x, &s0, 8);
            memcpy(&o.z, &s1, 8);
            *(float4*)(outp) = o;
            outp += HW;
        }
    }
}

extern "C" void kernel_launch(void* const* d_in, const int* in_sizes, int n_in,
                              void* d_out, int out_size)
{
    const float* input = (const float*)d_in[0];
    const float* wts   = (const float*)d_in[1];
    float* out         = (float*)d_out;

    // one CTA per plane; 4 pipelined bands of 32 rows
    hconv_dw_kernel<<<2048, 128>>>(input, wts, out);
}

// round 9
// speedup vs baseline: 1.1997x; 1.1997x over previous
#include <cuda_runtime.h>
#include <string.h>

// HyperConv2dDepthWise: per-batch-weight 5x5 depthwise conv + bias + SiLU
// input:  (16, 128, 128, 128) f32   -> 2048 planes of 128x128
// weights:(16, 3328) f32            -> per (b,c): 25 taps at b*3328+c*25, bias at b*3328+3200+c
// output: (16, 128, 128, 128) f32
//
// Round-7: R4 structure (CTA = 32-row band, grid 8192 — best measured) with:
//  - cp.async.cg staging (zero-fill OOB), predicate-free path for interior bands
//  - __launch_bounds__(128, 6) -> regs <= 85 -> 6 CTAs/SM
//  - horizontal f32x2 packing, 5-row packed sliding window, tanh packed SiLU

#define HW      128
#define BAND    32
#define SROWS   (BAND + 4)     // 36
#define SPITCH  136            // floats; logical col L lives at smem col L+4
#define WSTRIDE 3328           // 25*128 + 128
#define BOFF    3200           // 25*128

typedef unsigned long long ull;

__device__ __forceinline__ ull pair_of(float lo, float hi) {
    float2 t = make_float2(lo, hi);
    ull r;
    memcpy(&r, &t, 8);
    return r;
}
__device__ __forceinline__ void fma2(ull& d, ull a, ull b) {
    asm("fma.rn.f32x2 %0, %1, %2, %0;" : "+l"(d) : "l"(a), "l"(b));
}
__device__ __forceinline__ float2 unpk(ull v) {
    float2 f;
    memcpy(&f, &v, 8);
    return f;
}

// packed SiLU: silu(x) = h + h*tanh(h), h = 0.5*x   (tanh.approx HW op)
__device__ __forceinline__ ull silu2(ull acc, ull half2c) {
    ull h2;
    asm("mul.rn.f32x2 %0, %1, %2;" : "=l"(h2) : "l"(acc), "l"(half2c));
    float2 h = unpk(h2);
    float t0, t1;
    asm("tanh.approx.f32 %0, %1;" : "=f"(t0) : "f"(h.x));
    asm("tanh.approx.f32 %0, %1;" : "=f"(t1) : "f"(h.y));
    ull t2 = pair_of(t0, t1);
    ull r;
    asm("fma.rn.f32x2 %0, %1, %2, %1;" : "=l"(r) : "l"(h2), "l"(t2));
    return r;
}

// One packed window row: covers logical cols x0-2 .. x0+5.
struct WRow {
    ull E0, E1, E2, E3, O0, O1, O2;
};

__device__ __forceinline__ WRow load_row(const float* __restrict__ p) {
    float4 A = *(const float4*)(p);      // logical x0-4 .. x0-1
    float4 B = *(const float4*)(p + 4);  // logical x0   .. x0+3
    float4 C = *(const float4*)(p + 8);  // logical x0+4 .. x0+7
    WRow r;
    memcpy(&r.E0, &A.z, 8);
    memcpy(&r.E1, &B.x, 8);
    memcpy(&r.E2, &B.z, 8);
    memcpy(&r.E3, &C.x, 8);
    r.O0 = pair_of(A.w, B.x);
    r.O1 = pair_of(B.y, B.z);
    r.O2 = pair_of(B.w, C.x);
    return r;
}

__device__ __forceinline__ void cpa16(float* dst_s, const float* src_g, int sz) {
    const unsigned dst = (unsigned)__cvta_generic_to_shared(dst_s);
    asm volatile("cp.async.cg.shared.global [%0], [%1], 16, %2;\n"
                 :: "r"(dst), "l"(src_g), "r"(sz));
}

__global__ __launch_bounds__(128, 6)
void hconv_dw_kernel(const float* __restrict__ input,
                     const float* __restrict__ wts,
                     float* __restrict__ out)
{
    __shared__ float smem[SROWS * SPITCH];

    const int bid   = blockIdx.x;
    const int band  = bid & 3;          // 4 bands of 32 rows per plane
    const int plane = bid >> 2;         // b*128 + c
    const int b     = plane >> 7;
    const int c     = plane & 127;
    const int r0    = band * BAND;

    const float* __restrict__ ip = input + (size_t)plane * (HW * HW);
    float* __restrict__ op       = out   + (size_t)plane * (HW * HW);

    const int tid = threadIdx.x;
    const int lq  = tid & 31;           // interior quad: logical col lq*4
    const int lr  = tid >> 5;           // 0..3

    // ---- stage band (+2-row halo) via cp.async; smem row y = global row r0+y-2
    {
        float* dst0 = smem + lr * SPITCH + 4 + lq * 4;
        const float* src0 = ip + (r0 + lr - 2) * HW + lq * 4;
        if (band == 0 || band == 3) {
            // edge bands: 2 OOB rows -> src-size 0 zero-fill
#pragma unroll
            for (int k = 0; k < 9; k++) {
                const int g = r0 + lr + k * 4 - 2;
                const bool ok = (g >= 0 && g < HW);
                cpa16(dst0 + k * 4 * SPITCH,
                      ip + (ok ? g : 0) * HW + lq * 4, ok ? 16 : 0);
            }
        } else {
            // interior bands: no predicates at all
#pragma unroll
            for (int k = 0; k < 9; k++)
                cpa16(dst0 + k * 4 * SPITCH, src0 + k * 4 * HW, 16);
        }
        asm volatile("cp.async.commit_group;\n" ::: "memory");

        // zero halo columns (quads 0 and 33) with plain STS meanwhile
        const float4 z4 = make_float4(0.f, 0.f, 0.f, 0.f);
        if (tid < 2 * SROWS) {
            const int y = tid >> 1;
            const int q = (tid & 1) ? 33 : 0;
            *(float4*)(smem + y * SPITCH + q * 4) = z4;
        }
    }

    // ---- per-plane weights (LDG latency overlaps the cp.async fill) ----
    const float* wp = wts + b * WSTRIDE + c * 25;
    ull w2[25];
#pragma unroll
    for (int t = 0; t < 25; t++) {
        const float w = __ldg(wp + t);
        w2[t] = pair_of(w, w);
    }
    const float bias = __ldg(wts + b * WSTRIDE + BOFF + c);
    const ull bias2  = pair_of(bias, bias);
    const ull half2c = pair_of(0.5f, 0.5f);

    asm volatile("cp.async.wait_group 0;\n" ::: "memory");
    __syncthreads();

    // ---- compute: warp = full row width, 32 lanes x 4 cols, 8 rows/warp ----
    const int warp = tid >> 5;          // 0..3
    const int x0   = lq * 4;            // logical output col base
    const int br0  = warp * 8;          // band-local first output row

    WRow win[5];
#pragma unroll
    for (int y = 0; y < 4; y++)
        win[y] = load_row(smem + (br0 + y) * SPITCH + x0);

    float* outp = op + (r0 + br0) * HW + x0;

#pragma unroll
    for (int i = 0; i < 8; i++) {
        // new bottom row -> ring slot (i+4)%5; consumed by last weight row
        win[(i + 4) % 5] = load_row(smem + (br0 + i + 4) * SPITCH + x0);

        ull acc0 = bias2, acc1 = bias2;
#pragma unroll
        for (int d = 0; d < 5; d++) {
            const WRow& r = win[(i + d) % 5];
            fma2(acc0, w2[d * 5 + 0], r.E0);  fma2(acc1, w2[d * 5 + 0], r.E1);
            fma2(acc0, w2[d * 5 + 1], r.O0);  fma2(acc1, w2[d * 5 + 1], r.O1);
            fma2(acc0, w2[d * 5 + 2], r.E1);  fma2(acc1, w2[d * 5 + 2], r.E2);
            fma2(acc0, w2[d * 5 + 3], r.O1);  fma2(acc1, w2[d * 5 + 3], r.O2);
            fma2(acc0, w2[d * 5 + 4], r.E2);  fma2(acc1, w2[d * 5 + 4], r.E3);
        }

        const ull s0 = silu2(acc0, half2c);
        const ull s1 = silu2(acc1, half2c);
        float4 o;
        memcpy(&o.x, &s0, 8);
        memcpy(&o.z, &s1, 8);
        *(float4*)(outp) = o;
        outp += HW;
    }
}

extern "C" void kernel_launch(void* const* d_in, const int* in_sizes, int n_in,
                              void* d_out, int out_size)
{
    const float* input = (const float*)d_in[0];
    const float* wts   = (const float*)d_in[1];
    float* out         = (float*)d_out;

    // 2048 planes x 4 bands of 32 rows
    hconv_dw_kernel<<<8192, 128>>>(input, wts, out);
}

// round 12
// speedup vs baseline: 1.2151x; 1.0128x over previous
#include <cuda_runtime.h>
#include <string.h>

// HyperConv2dDepthWise: per-batch-weight 5x5 depthwise conv + bias + SiLU
// input:  (16, 128, 128, 128) f32   -> 2048 planes of 128x128
// weights:(16, 3328) f32            -> per (b,c): 25 taps at b*3328+c*25, bias at b*3328+3200+c
// output: (16, 128, 128, 128) f32
//
// Round-9: SCATTER dataflow. Stream 12 input rows once; each row, when loaded,
// is scattered into the 5 in-flight output accumulators (o = y-4..y, d = y-o).
// Live state = 5 acc pairs + ONE row (~50 regs vs 70-reg gather window) ->
// __launch_bounds__(128,8) -> 8 CTAs/SM, 32 warps. cp.async staging,
// horizontal f32x2 packing, tanh packed SiLU unchanged from R7.

#define HW      128
#define BAND    32
#define SROWS   (BAND + 4)     // 36
#define SPITCH  136            // floats; logical col L lives at smem col L+4
#define WSTRIDE 3328           // 25*128 + 128
#define BOFF    3200           // 25*128

typedef unsigned long long ull;

__device__ __forceinline__ ull pair_of(float lo, float hi) {
    float2 t = make_float2(lo, hi);
    ull r;
    memcpy(&r, &t, 8);
    return r;
}
__device__ __forceinline__ void fma2(ull& d, ull a, ull b) {
    asm("fma.rn.f32x2 %0, %1, %2, %0;" : "+l"(d) : "l"(a), "l"(b));
}
__device__ __forceinline__ float2 unpk(ull v) {
    float2 f;
    memcpy(&f, &v, 8);
    return f;
}

// packed SiLU: silu(x) = h + h*tanh(h), h = 0.5*x   (tanh.approx HW op)
__device__ __forceinline__ ull silu2(ull acc, ull half2c) {
    ull h2;
    asm("mul.rn.f32x2 %0, %1, %2;" : "=l"(h2) : "l"(acc), "l"(half2c));
    float2 h = unpk(h2);
    float t0, t1;
    asm("tanh.approx.f32 %0, %1;" : "=f"(t0) : "f"(h.x));
    asm("tanh.approx.f32 %0, %1;" : "=f"(t1) : "f"(h.y));
    ull t2 = pair_of(t0, t1);
    ull r;
    asm("fma.rn.f32x2 %0, %1, %2, %1;" : "=l"(r) : "l"(h2), "l"(t2));
    return r;
}

// One packed row: covers logical cols x0-2 .. x0+5.
struct WRow {
    ull E0, E1, E2, E3, O0, O1, O2;
};

__device__ __forceinline__ WRow load_row(const float* __restrict__ p) {
    float4 A = *(const float4*)(p);      // logical x0-4 .. x0-1
    float4 B = *(const float4*)(p + 4);  // logical x0   .. x0+3
    float4 C = *(const float4*)(p + 8);  // logical x0+4 .. x0+7
    WRow r;
    memcpy(&r.E0, &A.z, 8);
    memcpy(&r.E1, &B.x, 8);
    memcpy(&r.E2, &B.z, 8);
    memcpy(&r.E3, &C.x, 8);
    r.O0 = pair_of(A.w, B.x);
    r.O1 = pair_of(B.y, B.z);
    r.O2 = pair_of(B.w, C.x);
    return r;
}

__device__ __forceinline__ void contrib(ull& a0, ull& a1, const WRow& r,
                                        const ull* __restrict__ w2, int d) {
    fma2(a0, w2[d * 5 + 0], r.E0);  fma2(a1, w2[d * 5 + 0], r.E1);
    fma2(a0, w2[d * 5 + 1], r.O0);  fma2(a1, w2[d * 5 + 1], r.O1);
    fma2(a0, w2[d * 5 + 2], r.E1);  fma2(a1, w2[d * 5 + 2], r.E2);
    fma2(a0, w2[d * 5 + 3], r.O1);  fma2(a1, w2[d * 5 + 3], r.O2);
    fma2(a0, w2[d * 5 + 4], r.E2);  fma2(a1, w2[d * 5 + 4], r.E3);
}

__device__ __forceinline__ void cpa16(float* dst_s, const float* src_g, int sz) {
    const unsigned dst = (unsigned)__cvta_generic_to_shared(dst_s);
    asm volatile("cp.async.cg.shared.global [%0], [%1], 16, %2;\n"
                 :: "r"(dst), "l"(src_g), "r"(sz));
}

__global__ __launch_bounds__(128, 8)
void hconv_dw_kernel(const float* __restrict__ input,
                     const float* __restrict__ wts,
                     float* __restrict__ out)
{
    __shared__ float smem[SROWS * SPITCH];

    const int bid   = blockIdx.x;
    const int band  = bid & 3;          // 4 bands of 32 rows per plane
    const int plane = bid >> 2;         // b*128 + c
    const int b     = plane >> 7;
    const int c     = plane & 127;
    const int r0    = band * BAND;

    const float* __restrict__ ip = input + (size_t)plane * (HW * HW);
    float* __restrict__ op       = out   + (size_t)plane * (HW * HW);

    const int tid = threadIdx.x;
    const int lq  = tid & 31;           // interior quad: logical col lq*4
    const int lr  = tid >> 5;           // 0..3

    // ---- stage band (+2-row halo) via cp.async; smem row y = global row r0+y-2
    {
        float* dst0 = smem + lr * SPITCH + 4 + lq * 4;
        const float* src0 = ip + (r0 + lr - 2) * HW + lq * 4;
        if (band == 0 || band == 3) {
#pragma unroll
            for (int k = 0; k < 9; k++) {
                const int g = r0 + lr + k * 4 - 2;
                const bool ok = (g >= 0 && g < HW);
                cpa16(dst0 + k * 4 * SPITCH,
                      ip + (ok ? g : 0) * HW + lq * 4, ok ? 16 : 0);
            }
        } else {
#pragma unroll
            for (int k = 0; k < 9; k++)
                cpa16(dst0 + k * 4 * SPITCH, src0 + k * 4 * HW, 16);
        }
        asm volatile("cp.async.commit_group;\n" ::: "memory");

        // zero halo columns (quads 0 and 33) with plain STS meanwhile
        const float4 z4 = make_float4(0.f, 0.f, 0.f, 0.f);
        if (tid < 2 * SROWS) {
            const int y = tid >> 1;
            const int q = (tid & 1) ? 33 : 0;
            *(float4*)(smem + y * SPITCH + q * 4) = z4;
        }
    }

    // ---- per-plane weights (uniform across CTA -> uniform regs) ----
    const float* wp = wts + b * WSTRIDE + c * 25;
    ull w2[25];
#pragma unroll
    for (int t = 0; t < 25; t++) {
        const float w = __ldg(wp + t);
        w2[t] = pair_of(w, w);
    }
    const float bias = __ldg(wts + b * WSTRIDE + BOFF + c);
    const ull bias2  = pair_of(bias, bias);
    const ull half2c = pair_of(0.5f, 0.5f);

    asm volatile("cp.async.wait_group 0;\n" ::: "memory");
    __syncthreads();

    // ---- scatter compute: warp = full row width, 8 output rows per warp ----
    const int warp = tid >> 5;          // 0..3
    const int x0   = lq * 4;            // logical output col base
    const int br0  = warp * 8;          // band-local first output row

    const float* srow = smem + br0 * SPITCH + x0;
    float* outp = op + (r0 + br0) * HW + x0;

    // ring of 5 in-flight accumulator pairs, indexed by output row % 5
    ull acc[5][2];

#pragma unroll
    for (int rr = 0; rr < 12; rr++) {
        // smem row br0+rr = global input row r0+br0+rr-2;
        // contributes to band-local outputs o = rr-4 .. rr with d = rr-o.
        const WRow row = load_row(srow + rr * SPITCH);

        if (rr <= 7) {                  // birth of output rr
            acc[rr % 5][0] = bias2;
            acc[rr % 5][1] = bias2;
        }

#pragma unroll
        for (int d = 0; d < 5; d++) {
            const int o = rr - d;
            if (o >= 0 && o <= 7)
                contrib(acc[o % 5][0], acc[o % 5][1], row, w2, d);
        }

        if (rr >= 4) {                  // output rr-4 complete
            const int o = rr - 4;
            const ull s0 = silu2(acc[o % 5][0], half2c);
            const ull s1 = silu2(acc[o % 5][1], half2c);
            float4 v;
            memcpy(&v.x, &s0, 8);
            memcpy(&v.z, &s1, 8);
            *(float4*)(outp + o * HW) = v;
        }
    }
}

extern "C" void kernel_launch(void* const* d_in, const int* in_sizes, int n_in,
                              void* d_out, int out_size)
{
    const float* input = (const float*)d_in[0];
    const float* wts   = (const float*)d_in[1];
    float* out         = (float*)d_out;

    // 2048 planes x 4 bands of 32 rows
    hconv_dw_kernel<<<8192, 128>>>(input, wts, out);
}

// round 13
// speedup vs baseline: 1.2216x; 1.0054x over previous
#include <cuda_runtime.h>
#include <string.h>

// HyperConv2dDepthWise: per-batch-weight 5x5 depthwise conv + bias + SiLU
// input:  (16, 128, 128, 128) f32   -> 2048 planes of 128x128
// weights:(16, 3328) f32            -> per (b,c): 25 taps at b*3328+c*25, bias at b*3328+3200+c
// output: (16, 128, 128, 128) f32
//
// Round-12: scatter dataflow + CTA-uniform packed weights in SHARED MEMORY
// (was: 50 regs/thread of replicated weight pairs -> hidden spills/remat).
// Weight groups loaded per (row,d) via broadcast LDS (conflict-free). Output
// stored with __stcs (streaming) to keep L2 for input halo reuse.

#define HW      128
#define BAND    32
#define SROWS   (BAND + 4)     // 36
#define SPITCH  136            // floats; logical col L lives at smem col L+4
#define WSTRIDE 3328           // 25*128 + 128
#define BOFF    3200           // 25*128

typedef unsigned long long ull;

__device__ __forceinline__ ull pair_of(float lo, float hi) {
    float2 t = make_float2(lo, hi);
    ull r;
    memcpy(&r, &t, 8);
    return r;
}
__device__ __forceinline__ void fma2(ull& d, ull a, ull b) {
    asm("fma.rn.f32x2 %0, %1, %2, %0;" : "+l"(d) : "l"(a), "l"(b));
}
__device__ __forceinline__ float2 unpk(ull v) {
    float2 f;
    memcpy(&f, &v, 8);
    return f;
}

// packed SiLU: silu(x) = h + h*tanh(h), h = 0.5*x   (tanh.approx HW op)
__device__ __forceinline__ ull silu2(ull acc, ull half2c) {
    ull h2;
    asm("mul.rn.f32x2 %0, %1, %2;" : "=l"(h2) : "l"(acc), "l"(half2c));
    float2 h = unpk(h2);
    float t0, t1;
    asm("tanh.approx.f32 %0, %1;" : "=f"(t0) : "f"(h.x));
    asm("tanh.approx.f32 %0, %1;" : "=f"(t1) : "f"(h.y));
    ull t2 = pair_of(t0, t1);
    ull r;
    asm("fma.rn.f32x2 %0, %1, %2, %1;" : "=l"(r) : "l"(h2), "l"(t2));
    return r;
}

// One packed row: covers logical cols x0-2 .. x0+5.
struct WRow {
    ull E0, E1, E2, E3, O0, O1, O2;
};

__device__ __forceinline__ WRow load_row(const float* __restrict__ p) {
    float4 A = *(const float4*)(p);      // logical x0-4 .. x0-1
    float4 B = *(const float4*)(p + 4);  // logical x0   .. x0+3
    float4 C = *(const float4*)(p + 8);  // logical x0+4 .. x0+7
    WRow r;
    memcpy(&r.E0, &A.z, 8);
    memcpy(&r.E1, &B.x, 8);
    memcpy(&r.E2, &B.z, 8);
    memcpy(&r.E3, &C.x, 8);
    r.O0 = pair_of(A.w, B.x);
    r.O1 = pair_of(B.y, B.z);
    r.O2 = pair_of(B.w, C.x);
    return r;
}

__device__ __forceinline__ void contrib5(ull& a0, ull& a1, const WRow& r,
                                         ull w0, ull w1, ull wc, ull w3, ull w4) {
    fma2(a0, w0, r.E0);  fma2(a1, w0, r.E1);
    fma2(a0, w1, r.O0);  fma2(a1, w1, r.O1);
    fma2(a0, wc, r.E1);  fma2(a1, wc, r.E2);
    fma2(a0, w3, r.O1);  fma2(a1, w3, r.O2);
    fma2(a0, w4, r.E2);  fma2(a1, w4, r.E3);
}

__device__ __forceinline__ void cpa16(float* dst_s, const float* src_g, int sz) {
    const unsigned dst = (unsigned)__cvta_generic_to_shared(dst_s);
    asm volatile("cp.async.cg.shared.global [%0], [%1], 16, %2;\n"
                 :: "r"(dst), "l"(src_g), "r"(sz));
}

__global__ __launch_bounds__(128, 8)
void hconv_dw_kernel(const float* __restrict__ input,
                     const float* __restrict__ wts,
                     float* __restrict__ out)
{
    __shared__ float smem[SROWS * SPITCH];
    __shared__ alignas(16) ull wsm[5][8];   // 5 weight-row groups, padded to 64B

    const int bid   = blockIdx.x;
    const int band  = bid & 3;          // 4 bands of 32 rows per plane
    const int plane = bid >> 2;         // b*128 + c
    const int b     = plane >> 7;
    const int c     = plane & 127;
    const int r0    = band * BAND;

    const float* __restrict__ ip = input + (size_t)plane * (HW * HW);
    float* __restrict__ op       = out   + (size_t)plane * (HW * HW);

    const int tid = threadIdx.x;
    const int lq  = tid & 31;           // interior quad: logical col lq*4
    const int lr  = tid >> 5;           // 0..3

    // ---- stage band (+2-row halo) via cp.async; smem row y = global row r0+y-2
    {
        float* dst0 = smem + lr * SPITCH + 4 + lq * 4;
        const float* src0 = ip + (r0 + lr - 2) * HW + lq * 4;
        if (band == 0 || band == 3) {
#pragma unroll
            for (int k = 0; k < 9; k++) {
                const int g = r0 + lr + k * 4 - 2;
                const bool ok = (g >= 0 && g < HW);
                cpa16(dst0 + k * 4 * SPITCH,
                      ip + (ok ? g : 0) * HW + lq * 4, ok ? 16 : 0);
            }
        } else {
#pragma unroll
            for (int k = 0; k < 9; k++)
                cpa16(dst0 + k * 4 * SPITCH, src0 + k * 4 * HW, 16);
        }
        asm volatile("cp.async.commit_group;\n" ::: "memory");

        // zero halo columns (quads 0 and 33) with plain STS meanwhile
        const float4 z4 = make_float4(0.f, 0.f, 0.f, 0.f);
        if (tid < 2 * SROWS) {
            const int y = tid >> 1;
            const int q = (tid & 1) ? 33 : 0;
            *(float4*)(smem + y * SPITCH + q * 4) = z4;
        }
    }

    // ---- CTA-uniform packed weights -> shared (one pair per thread t<25) ----
    if (tid < 25) {
        const float w = __ldg(wts + b * WSTRIDE + c * 25 + tid);
        wsm[tid / 5][tid % 5] = pair_of(w, w);
    }
    const float bias = __ldg(wts + b * WSTRIDE + BOFF + c);
    const ull bias2  = pair_of(bias, bias);
    const ull half2c = pair_of(0.5f, 0.5f);

    asm volatile("cp.async.wait_group 0;\n" ::: "memory");
    __syncthreads();                    // band data + weights visible

    // ---- scatter compute: warp = full row width, 8 output rows per warp ----
    const int warp = tid >> 5;          // 0..3
    const int x0   = lq * 4;            // logical output col base
    const int br0  = warp * 8;          // band-local first output row

    const float* srow = smem + br0 * SPITCH + x0;
    float* outp = op + (r0 + br0) * HW + x0;

    // ring of 5 in-flight accumulator pairs, indexed by output row % 5
    ull acc[5][2];

#pragma unroll
    for (int rr = 0; rr < 12; rr++) {
        // smem row br0+rr = global input row r0+br0+rr-2;
        // contributes to band-local outputs o = rr-4 .. rr with d = rr-o.
        const WRow row = load_row(srow + rr * SPITCH);

        if (rr <= 7) {                  // birth of output rr
            acc[rr % 5][0] = bias2;
            acc[rr % 5][1] = bias2;
        }

#pragma unroll
        for (int d = 0; d < 5; d++) {
            const int o = rr - d;
            if (o >= 0 && o <= 7) {
                // broadcast loads of weight group d (conflict-free)
                const ulonglong2 p01 = *(const ulonglong2*)&wsm[d][0];
                const ulonglong2 p23 = *(const ulonglong2*)&wsm[d][2];
                const ull w4 = wsm[d][4];
                contrib5(acc[o % 5][0], acc[o % 5][1], row,
                         p01.x, p01.y, p23.x, p23.y, w4);
            }
        }

        if (rr >= 4) {                  // output rr-4 complete
            const int o = rr - 4;
            const ull s0 = silu2(acc[o % 5][0], half2c);
            const ull s1 = silu2(acc[o % 5][1], half2c);
            float4 v;
            memcpy(&v.x, &s0, 8);
            memcpy(&v.z, &s1, 8);
            __stcs((float4*)(outp + o * HW), v);   // streaming store
        }
    }
}

extern "C" void kernel_launch(void* const* d_in, const int* in_sizes, int n_in,
                              void* d_out, int out_size)
{
    const float* input = (const float*)d_in[0];
    const float* wts   = (const float*)d_in[1];
    float* out         = (float*)d_out;

    // 2048 planes x 4 bands of 32 rows
    hconv_dw_kernel<<<8192, 128>>>(input, wts, out);
}